// round 16
// baseline (speedup 1.0000x reference)
#include <cuda_runtime.h>
#include <cstdint>

#define N_EDGES 3200000
#define N_NODES 100000
#define TPB 256
#define GRID_BLOCKS (N_EDGES / TPB)                 // 12500
#define PAD_BLOCKS ((N_NODES + TPB - 1) / TPB)      // 391

// 16B-aligned padded copy of pos: one LDG.128 per gather instead of 3 LDG.32.
__device__ float4 g_pos_pad[N_NODES];
// device-side dependency: number of pad blocks completed (self-resets each launch)
__device__ int g_pad_done;
__device__ int g_exit_cnt;

__global__ __launch_bounds__(256)
void sh_edge_attrs_fused_kernel(const float4* __restrict__ pos4,
                                const void* __restrict__ edge_index_raw,
                                const float* __restrict__ shift,
                                float* __restrict__ out)
{
    __shared__ alignas(16) float s_shift[TPB * 3];            // 3072 B
    __shared__ alignas(16) float s_vec[TPB * 3];              // 3072 B
    __shared__ alignas(16) float s_len[TPB];                  // 1024 B
    __shared__ alignas(16) float s_sh[TPB * 9];               // 9216 B (also pad staging)
    __shared__ alignas(8)  unsigned long long s_mbar;

    const int t   = threadIdx.x;
    const int bid = blockIdx.x;
    const long long blk_base = (long long)bid * TPB;
    const long long e = blk_base + t;

    const uint32_t mbar = (uint32_t)__cvta_generic_to_shared(&s_mbar);

    if (t == 0) {
        asm volatile("mbarrier.init.shared.b64 [%0], 1;" :: "r"(mbar) : "memory");
    }

    // ---- pad phase: first PAD_BLOCKS blocks build g_pos_pad (staged in s_sh) ----
    if (bid < PAD_BLOCKS) {
        const int base_f4 = bid * 192;   // 192 float4 = 768 floats = 256 nodes
        if (t < 192) {
            const int idx = base_f4 + t;
            if (idx < (3 * N_NODES) / 4) ((float4*)s_sh)[t] = pos4[idx];
        }
        __syncthreads();
        const int node = bid * 256 + t;
        if (node < N_NODES) {
            g_pos_pad[node] = make_float4(s_sh[t * 3 + 0], s_sh[t * 3 + 1],
                                          s_sh[t * 3 + 2], 0.0f);
        }
        __syncthreads();   // pad writes issued; s_sh reusable below
        if (t == 0) {
            __threadfence();                 // release: pad data visible GPU-wide
            atomicAdd(&g_pad_done, 1);
        }
    }

    __syncthreads();   // mbar init visible to all warps (and pad smem settled)

    // ---- async bulk load of this block's shift tile (pad-independent) ----
    if (t == 0) {
        asm volatile("mbarrier.arrive.expect_tx.shared.b64 _, [%0], %1;"
                     :: "r"(mbar), "r"((unsigned)(TPB * 3 * 4)) : "memory");
        const uint32_t sdst = (uint32_t)__cvta_generic_to_shared(s_shift);
        asm volatile(
            "cp.async.bulk.shared::cta.global.mbarrier::complete_tx::bytes [%0], [%1], %2, [%3];"
            :: "r"(sdst), "l"(shift + blk_base * 3), "r"((unsigned)(TPB * 3 * 4)), "r"(mbar)
            : "memory");
    }

    // ---- dtype probe + edge indices (pad-independent, issue before the spin) ----
    const unsigned long long* p64 = (const unsigned long long*)edge_index_raw;
    const bool is64 = (((p64[0] | p64[1] | p64[2] | p64[3]) >> 32) == 0ULL);

    int src, dst;
    if (is64) {
        const long long* ei = (const long long*)edge_index_raw;
        src = (int)ei[e];
        dst = (int)ei[N_EDGES + e];
    } else {
        const int* ei = (const int*)edge_index_raw;
        src = ei[e];
        dst = ei[N_EDGES + e];
    }
    src = min(N_NODES - 1, max(0, src));
    dst = min(N_NODES - 1, max(0, dst));

    // ---- wait for pad completion (leader acquire-spin + block barrier) ----
    if (t == 0) {
        int v;
        do {
            asm volatile("ld.acquire.gpu.global.b32 %0, [%1];"
                         : "=r"(v) : "l"(&g_pad_done) : "memory");
            if (v < PAD_BLOCKS) __nanosleep(64);
        } while (v < PAD_BLOCKS);
    }
    __syncthreads();

    // ---- pos gathers: COHERENT 16B loads (first touch after acquire -> L2-correct).
    //      NOT __ldg: ld.global.nc is invalid for data written in this launch. ----
    const float4 pd = g_pos_pad[dst];
    const float4 ps = g_pos_pad[src];

    // ---- wait for shift tile ----
    {
        uint32_t done;
        asm volatile(
            "{\n\t"
            ".reg .pred p;\n\t"
            "mbarrier.try_wait.parity.acquire.cta.shared::cta.b64 p, [%1], 0;\n\t"
            "selp.b32 %0, 1, 0, p;\n\t"
            "}"
            : "=r"(done) : "r"(mbar) : "memory");
        if (!done) {
            asm volatile(
                "{\n\t"
                ".reg .pred P1;\n\t"
                "WAIT_LOOP_%=:\n\t"
                "mbarrier.try_wait.parity.acquire.cta.shared::cta.b64 P1, [%0], 0, 0x989680;\n\t"
                "@P1 bra.uni WAIT_DONE_%=;\n\t"
                "bra.uni WAIT_LOOP_%=;\n\t"
                "WAIT_DONE_%=:\n\t"
                "}"
                :: "r"(mbar) : "memory");
        }
    }

    const float sx = s_shift[t * 3 + 0];
    const float sy = s_shift[t * 3 + 1];
    const float sz = s_shift[t * 3 + 2];

    const float vx = pd.x - ps.x - sx;
    const float vy = pd.y - ps.y - sy;
    const float vz = pd.z - ps.z - sz;

    const float n2   = vx * vx + vy * vy + vz * vz;
    const float rinv = rsqrtf(n2);
    const float len  = n2 * rinv;

    const float x = vx * rinv;
    const float y = vy * rinv;
    const float z = vz * rinv;

    const float SQRT3 = 1.7320508075688772f;
    const float SQRT5 = 2.2360679774997896f;
    const float x2 = x * x, y2 = y * y, z2 = z * z;

    // ---- stage results (odd strides -> bank-conflict-free) ----
    s_vec[t * 3 + 0] = vx;
    s_vec[t * 3 + 1] = vy;
    s_vec[t * 3 + 2] = vz;
    s_len[t] = len;

    float* shl = s_sh + t * 9;
    shl[0] = 1.0f;
    shl[1] = SQRT3 * x;
    shl[2] = SQRT3 * y;
    shl[3] = SQRT3 * z;
    shl[4] = SQRT5 * (SQRT3 * x * z);
    shl[5] = SQRT5 * (SQRT3 * x * y);
    shl[6] = SQRT5 * (y2 - 0.5f * (x2 + z2));
    shl[7] = SQRT5 * (SQRT3 * y * z);
    shl[8] = SQRT5 * (0.5f * SQRT3 * (z2 - x2));

    __syncthreads();

    // ---- async bulk stores: TMA reads smem directly, no L1 wavefronts ----
    if (t == 0) {
        asm volatile("fence.proxy.async.shared::cta;" ::: "memory");

        const uint32_t svec = (uint32_t)__cvta_generic_to_shared(s_vec);
        const uint32_t slen = (uint32_t)__cvta_generic_to_shared(s_len);
        const uint32_t ssh  = (uint32_t)__cvta_generic_to_shared(s_sh);

        float* gvec = out + blk_base * 3;
        float* glen = out + 3LL * N_EDGES + blk_base;
        float* gsh  = out + 4LL * N_EDGES + blk_base * 9;

        asm volatile("cp.async.bulk.global.shared::cta.bulk_group [%0], [%1], %2;"
                     :: "l"(gvec), "r"(svec), "r"((unsigned)(TPB * 3 * 4)) : "memory");
        asm volatile("cp.async.bulk.global.shared::cta.bulk_group [%0], [%1], %2;"
                     :: "l"(glen), "r"(slen), "r"((unsigned)(TPB * 4)) : "memory");
        asm volatile("cp.async.bulk.global.shared::cta.bulk_group [%0], [%1], %2;"
                     :: "l"(gsh), "r"(ssh), "r"((unsigned)(TPB * 9 * 4)) : "memory");
        asm volatile("cp.async.bulk.commit_group;" ::: "memory");
        asm volatile("cp.async.bulk.wait_group 0;" ::: "memory");

        // ---- self-reset of counters: last exiting block zeroes both ----
        const int n = atomicAdd(&g_exit_cnt, 1);
        if (n == GRID_BLOCKS - 1) {
            atomicExch(&g_exit_cnt, 0);
            atomicExch(&g_pad_done, 0);
        }
    }
}

extern "C" void kernel_launch(void* const* d_in, const int* in_sizes, int n_in,
                              void* d_out, int out_size)
{
    // Identify inputs by element count (robust to metadata ordering):
    //   pos: 300000 floats, edge_index: 6400000 ints, shift: 9600000 floats
    const float* pos        = nullptr;
    const void*  edge_index = nullptr;
    const float* shift      = nullptr;

    for (int i = 0; i < n_in; i++) {
        if (in_sizes[i] == 3 * N_NODES)      pos        = (const float*)d_in[i];
        else if (in_sizes[i] == 2 * N_EDGES) edge_index = (const void*)d_in[i];
        else if (in_sizes[i] == 3 * N_EDGES) shift      = (const float*)d_in[i];
    }

    float* out = (float*)d_out;

    sh_edge_attrs_fused_kernel<<<GRID_BLOCKS, TPB>>>((const float4*)pos,
                                                     edge_index, shift, out);
}

// round 17
// speedup vs baseline: 1.1023x; 1.1023x over previous
#include <cuda_runtime.h>
#include <cstdint>

#define N_EDGES 3200000
#define N_NODES 100000
#define TPB 256

// 16B-aligned padded copy of pos: one LDG.128 per gather instead of 3 LDG.32.
__device__ float4 g_pos_pad[N_NODES];
// edge_index dtype flag, set by pad kernel: 1 = int64, 0 = int32
__device__ int g_is64;

// Vectorized pad: 256 nodes per block; also probes edge_index dtype once.
__global__ __launch_bounds__(256)
void pos_pad_kernel(const float4* __restrict__ pos4,
                    const unsigned long long* __restrict__ ei64)
{
    __shared__ float s[768];
    const int t = threadIdx.x;
    const int base_node = blockIdx.x * 256;
    const int base_f4   = blockIdx.x * 192;

    if (blockIdx.x == 0 && t == 0) {
        // int64 indices (<2^32) have zero high halves
        g_is64 = (((ei64[0] | ei64[1] | ei64[2] | ei64[3]) >> 32) == 0ULL) ? 1 : 0;
    }

    if (t < 192) {
        const int idx = base_f4 + t;
        if (idx < (3 * N_NODES) / 4) ((float4*)s)[t] = pos4[idx];
    }
    __syncthreads();

    const int node = base_node + t;
    if (node < N_NODES) {
        g_pos_pad[node] = make_float4(s[t * 3 + 0], s[t * 3 + 1], s[t * 3 + 2], 0.0f);
    }
}

__global__ __launch_bounds__(256)
void sh_edge_attrs_kernel(const void* __restrict__ edge_index_raw,
                          const float* __restrict__ shift,
                          float* __restrict__ out)
{
    __shared__ alignas(16) float s_shift[TPB * 3];            // 3072 B
    __shared__ alignas(16) float s_vec[TPB * 3];              // 3072 B
    __shared__ alignas(16) float s_len[TPB];                  // 1024 B
    __shared__ alignas(16) float s_sh[TPB * 9];               // 9216 B
    __shared__ alignas(8)  unsigned long long s_mbar;

    const int t = threadIdx.x;
    const long long blk_base = (long long)blockIdx.x * TPB;
    const long long e = blk_base + t;

    const uint32_t mbar = (uint32_t)__cvta_generic_to_shared(&s_mbar);

    // broadcast flag load issued pre-barrier so index LDGs dispatch right after sync
    const int is64 = g_is64;

    if (t == 0) {
        asm volatile("mbarrier.init.shared.b64 [%0], 1;" :: "r"(mbar) : "memory");
    }
    __syncthreads();

    // ---- edge indices first: longest-latency loads go out earliest ----
    int src, dst;
    if (is64) {
        const long long* ei = (const long long*)edge_index_raw;
        src = (int)ei[e];
        dst = (int)ei[N_EDGES + e];
    } else {
        const int* ei = (const int*)edge_index_raw;
        src = ei[e];
        dst = ei[N_EDGES + e];
    }
    src = min(N_NODES - 1, max(0, src));
    dst = min(N_NODES - 1, max(0, dst));

    // ---- pos gathers: single 16B load per node ----
    const float4 pd = __ldg(&g_pos_pad[dst]);
    const float4 ps = __ldg(&g_pos_pad[src]);

    // ---- async bulk load of this block's shift tile (bypasses L1 wavefronts) ----
    if (t == 0) {
        asm volatile("mbarrier.arrive.expect_tx.shared.b64 _, [%0], %1;"
                     :: "r"(mbar), "r"((unsigned)(TPB * 3 * 4)) : "memory");
        const uint32_t sdst = (uint32_t)__cvta_generic_to_shared(s_shift);
        asm volatile(
            "cp.async.bulk.shared::cta.global.mbarrier::complete_tx::bytes [%0], [%1], %2, [%3];"
            :: "r"(sdst), "l"(shift + blk_base * 3), "r"((unsigned)(TPB * 3 * 4)), "r"(mbar)
            : "memory");
    }

    // ---- wait for shift tile ----
    {
        uint32_t done;
        asm volatile(
            "{\n\t"
            ".reg .pred p;\n\t"
            "mbarrier.try_wait.parity.acquire.cta.shared::cta.b64 p, [%1], 0;\n\t"
            "selp.b32 %0, 1, 0, p;\n\t"
            "}"
            : "=r"(done) : "r"(mbar) : "memory");
        if (!done) {
            asm volatile(
                "{\n\t"
                ".reg .pred P1;\n\t"
                "WAIT_LOOP_%=:\n\t"
                "mbarrier.try_wait.parity.acquire.cta.shared::cta.b64 P1, [%0], 0, 0x989680;\n\t"
                "@P1 bra.uni WAIT_DONE_%=;\n\t"
                "bra.uni WAIT_LOOP_%=;\n\t"
                "WAIT_DONE_%=:\n\t"
                "}"
                :: "r"(mbar) : "memory");
        }
    }

    const float sx = s_shift[t * 3 + 0];
    const float sy = s_shift[t * 3 + 1];
    const float sz = s_shift[t * 3 + 2];

    const float vx = pd.x - ps.x - sx;
    const float vy = pd.y - ps.y - sy;
    const float vz = pd.z - ps.z - sz;

    const float n2   = vx * vx + vy * vy + vz * vz;
    const float rinv = rsqrtf(n2);
    const float len  = n2 * rinv;

    const float x = vx * rinv;
    const float y = vy * rinv;
    const float z = vz * rinv;

    const float SQRT3 = 1.7320508075688772f;
    const float SQRT5 = 2.2360679774997896f;
    const float x2 = x * x, y2 = y * y, z2 = z * z;

    // ---- stage results (odd strides -> bank-conflict-free) ----
    s_vec[t * 3 + 0] = vx;
    s_vec[t * 3 + 1] = vy;
    s_vec[t * 3 + 2] = vz;
    s_len[t] = len;

    float* shl = s_sh + t * 9;
    shl[0] = 1.0f;
    shl[1] = SQRT3 * x;
    shl[2] = SQRT3 * y;
    shl[3] = SQRT3 * z;
    shl[4] = SQRT5 * (SQRT3 * x * z);
    shl[5] = SQRT5 * (SQRT3 * x * y);
    shl[6] = SQRT5 * (y2 - 0.5f * (x2 + z2));
    shl[7] = SQRT5 * (SQRT3 * y * z);
    shl[8] = SQRT5 * (0.5f * SQRT3 * (z2 - x2));

    __syncthreads();

    // ---- async bulk stores: TMA reads smem directly, no L1 wavefronts ----
    if (t == 0) {
        asm volatile("fence.proxy.async.shared::cta;" ::: "memory");

        const uint32_t svec = (uint32_t)__cvta_generic_to_shared(s_vec);
        const uint32_t slen = (uint32_t)__cvta_generic_to_shared(s_len);
        const uint32_t ssh  = (uint32_t)__cvta_generic_to_shared(s_sh);

        float* gvec = out + blk_base * 3;
        float* glen = out + 3LL * N_EDGES + blk_base;
        float* gsh  = out + 4LL * N_EDGES + blk_base * 9;

        asm volatile("cp.async.bulk.global.shared::cta.bulk_group [%0], [%1], %2;"
                     :: "l"(gvec), "r"(svec), "r"((unsigned)(TPB * 3 * 4)) : "memory");
        asm volatile("cp.async.bulk.global.shared::cta.bulk_group [%0], [%1], %2;"
                     :: "l"(glen), "r"(slen), "r"((unsigned)(TPB * 4)) : "memory");
        asm volatile("cp.async.bulk.global.shared::cta.bulk_group [%0], [%1], %2;"
                     :: "l"(gsh), "r"(ssh), "r"((unsigned)(TPB * 9 * 4)) : "memory");
        asm volatile("cp.async.bulk.commit_group;" ::: "memory");
        asm volatile("cp.async.bulk.wait_group 0;" ::: "memory");
    }
}

extern "C" void kernel_launch(void* const* d_in, const int* in_sizes, int n_in,
                              void* d_out, int out_size)
{
    // Identify inputs by element count (robust to metadata ordering):
    //   pos: 300000 floats, edge_index: 6400000 ints, shift: 9600000 floats
    const float* pos        = nullptr;
    const void*  edge_index = nullptr;
    const float* shift      = nullptr;

    for (int i = 0; i < n_in; i++) {
        if (in_sizes[i] == 3 * N_NODES)      pos        = (const float*)d_in[i];
        else if (in_sizes[i] == 2 * N_EDGES) edge_index = (const void*)d_in[i];
        else if (in_sizes[i] == 3 * N_EDGES) shift      = (const float*)d_in[i];
    }

    float* out = (float*)d_out;

    const int pad_blocks = (N_NODES + 255) / 256;   // 391
    pos_pad_kernel<<<pad_blocks, 256>>>((const float4*)pos,
                                        (const unsigned long long*)edge_index);

    const int blocks = N_EDGES / TPB;   // 12500, exact
    sh_edge_attrs_kernel<<<blocks, TPB>>>(edge_index, shift, out);
}